// round 1
// baseline (speedup 1.0000x reference)
#include <cuda_runtime.h>
#include <math.h>

// Problem constants (fixed by the bench problem)
#define AA     48          // atoms per batch
#define SS     4           // num species
#define NR     16          // num radial shifts (ShfR)
#define NAA    4           // num angular radial shifts (ShfA)
#define NZ     8           // num angular shifts (ShfZ)
#define NPAIRS (SS*(SS+1)/2)   // 10
#define RADD   (SS*NR)         // 64
#define ANGD   (NPAIRS*NAA*NZ) // 320
#define OUTD   (RADD+ANGD)     // 384
#define RCR    5.2f
#define RCA    3.5f
#define PI_F   3.14159265358979323846f

__global__ __launch_bounds__(128) void aev_kernel(
    const int*   __restrict__ species,   // [B, A]
    const float* __restrict__ coords,    // [B, A, 3]
    const float* __restrict__ EtaR,      // [1]
    const float* __restrict__ ShfR,      // [NR]
    const float* __restrict__ EtaA,      // [1]
    const float* __restrict__ Zeta,      // [1]
    const float* __restrict__ ShfA,      // [NAA]
    const float* __restrict__ ShfZ,      // [NZ]
    float*       __restrict__ out)       // [B, A, OUTD]
{
    __shared__ float cxs[AA], cys[AA], czs_[AA];
    __shared__ int   sp[AA];
    __shared__ float dxs[AA], dys[AA], dzs[AA], dst[AA], fcr[AA], fca[AA];
    __shared__ int   nbr[AA];
    __shared__ int   nNbr;
    __shared__ float acc[OUTD];
    __shared__ float shfR_s[NR], shfA_s[NAA], czZ[NZ], szZ[NZ];
    __shared__ float etaR_s, etaA_s, zeta_s;

    const int tid = threadIdx.x;
    const int bd  = blockDim.x;
    const int i   = blockIdx.x % AA;
    const int b   = blockIdx.x / AA;

    if (tid == 0) {
        nNbr   = 0;
        etaR_s = EtaR[0];
        etaA_s = EtaA[0];
        zeta_s = Zeta[0];
    }
    for (int t = tid; t < AA; t += bd) {
        cxs[t]  = coords[(b*AA + t)*3 + 0];
        cys[t]  = coords[(b*AA + t)*3 + 1];
        czs_[t] = coords[(b*AA + t)*3 + 2];
        sp[t]   = species[b*AA + t];
    }
    for (int t = tid; t < OUTD; t += bd) acc[t] = 0.0f;
    if (tid < NR)  shfR_s[tid] = ShfR[tid];
    if (tid < NAA) shfA_s[tid] = ShfA[tid];
    if (tid < NZ)  { float s = ShfZ[tid]; czZ[tid] = cosf(s); szZ[tid] = sinf(s); }
    __syncthreads();

    const bool  validI = (sp[i] >= 0);
    const float xi = cxs[i], yi = cys[i], zi = czs_[i];

    // Per-neighbor distances, cutoffs, compacted angular-neighbor list
    for (int j = tid; j < AA; j += bd) {
        float dx = xi - cxs[j], dy = yi - cys[j], dz = zi - czs_[j];
        float d  = sqrtf(dx*dx + dy*dy + dz*dz);
        dxs[j] = dx; dys[j] = dy; dzs[j] = dz; dst[j] = d;
        bool pv = validI && (sp[j] >= 0) && (j != i);
        fcr[j] = (pv && d <= RCR) ? (0.5f*cosf(PI_F * d / RCR) + 0.5f) : 0.0f;
        bool an = (pv && d <= RCA);
        fca[j] = an ? (0.5f*cosf(PI_F * d / RCA) + 0.5f) : 0.0f;
        if (an) { int s = atomicAdd(&nNbr, 1); nbr[s] = j; }
    }
    __syncthreads();

    // ---- Radial phase: work item = (j, r) ----
    const float etaR = etaR_s;
    for (int w = tid; w < AA*NR; w += bd) {
        int j = w >> 4;        // NR == 16
        int r = w & 15;
        float f = fcr[j];
        if (f > 0.0f) {
            float dd = dst[j] - shfR_s[r];
            float v  = 0.25f * expf(-etaR * dd * dd) * f;
            atomicAdd(&acc[sp[j]*NR + r], v);
        }
    }

    // ---- Angular phase: work item = one unordered neighbor pair (p < q) ----
    // reference: 0.5 * sum over ordered (j,k), j!=k; at is symmetric in (j,k),
    // so this equals the plain sum over unordered pairs.
    const int   M      = nNbr;
    const int   npair2 = M*(M-1)/2;
    const float etaA   = etaA_s;
    const float zeta   = zeta_s;
    for (int u = tid; u < npair2; u += bd) {
        int p = 0, rem = u;
        while (rem >= M - 1 - p) { rem -= M - 1 - p; p++; }
        int q  = p + 1 + rem;
        int jp = nbr[p], jq = nbr[q];

        float dp = dst[jp], dq = dst[jq];
        float dot = dxs[jp]*dxs[jq] + dys[jp]*dys[jq] + dzs[jp]*dzs[jq];
        float dd  = fmaxf(dp*dq, 1e-8f);
        float cosA = 0.95f * dot / dd;
        float sinA = sqrtf(fmaxf(1.0f - cosA*cosA, 0.0f));
        float dsum = 0.5f * (dp + dq);
        float w2   = 2.0f * fca[jp] * fca[jq];

        int s1 = sp[jp], s2 = sp[jq];
        int lo = min(s1, s2), hi = max(s1, s2);
        int pidx = lo*SS - (lo*(lo-1))/2 + (hi - lo);
        int base = RADD + pidx*(NAA*NZ);

        float f2v[NAA];
        #pragma unroll
        for (int a = 0; a < NAA; a++) {
            float t = dsum - shfA_s[a];
            f2v[a] = expf(-etaA * t * t);
        }

        #pragma unroll
        for (int z = 0; z < NZ; z++) {
            float x = 0.5f * (1.0f + cosA*czZ[z] + sinA*szZ[z]);
            float f1;
            if (zeta == 32.0f) {
                float x2 = x*x, x4 = x2*x2, x8 = x4*x4, x16 = x8*x8;
                f1 = x16*x16;
            } else {
                f1 = powf(x, zeta);
            }
            float f1w = f1 * w2;
            #pragma unroll
            for (int a = 0; a < NAA; a++) {
                atomicAdd(&acc[base + a*NZ + z], f1w * f2v[a]);
            }
        }
    }
    __syncthreads();

    // ---- Write out: [radial (64) | angular (320)] contiguous per atom ----
    float* o = out + (size_t)blockIdx.x * OUTD;
    for (int t = tid; t < OUTD; t += bd) o[t] = acc[t];
}

extern "C" void kernel_launch(void* const* d_in, const int* in_sizes, int n_in,
                              void* d_out, int out_size)
{
    const int*   species = (const int*)  d_in[0];
    const float* coords  = (const float*)d_in[1];
    const float* EtaR    = (const float*)d_in[2];
    const float* ShfR    = (const float*)d_in[3];
    const float* EtaA    = (const float*)d_in[4];
    const float* Zeta    = (const float*)d_in[5];
    const float* ShfA    = (const float*)d_in[6];
    const float* ShfZ    = (const float*)d_in[7];
    float* out = (float*)d_out;

    int B = in_sizes[0] / AA;   // species is [B, A]
    aev_kernel<<<B * AA, 128>>>(species, coords, EtaR, ShfR, EtaA, Zeta,
                                ShfA, ShfZ, out);
}

// round 2
// speedup vs baseline: 2.7536x; 2.7536x over previous
#include <cuda_runtime.h>
#include <math.h>

// Problem constants (fixed by the bench problem)
#define AA     48          // atoms per batch
#define SS     4           // num species
#define NR     16          // num radial shifts (ShfR)
#define NAA    4           // num angular radial shifts (ShfA)
#define NZ     8           // num angular shifts (ShfZ)
#define NPAIRS (SS*(SS+1)/2)   // 10
#define RADD   (SS*NR)         // 64
#define ANGD   (NPAIRS*NAA*NZ) // 320
#define OUTD   (RADD+ANGD)     // 384
#define RCR    5.2f
#define RCA    3.5f
#define PI_F   3.14159265358979323846f
#define PCHUNK 128             // angular pairs processed per chunk

__global__ __launch_bounds__(128) void aev_kernel(
    const int*   __restrict__ species,   // [B, A]
    const float* __restrict__ coords,    // [B, A, 3]
    const float* __restrict__ EtaR,      // [1]
    const float* __restrict__ ShfR,      // [NR]
    const float* __restrict__ EtaA,      // [1]
    const float* __restrict__ Zeta,      // [1]
    const float* __restrict__ ShfA,      // [NAA]
    const float* __restrict__ ShfZ,      // [NZ]
    float*       __restrict__ out)       // [B, A, OUTD]
{
    __shared__ float cxs[AA], cys[AA], czs_[AA];
    __shared__ int   sp[AA];
    __shared__ float dxs[AA], dys[AA], dzs[AA], dst[AA], fcr[AA], fca[AA];
    __shared__ int   nbr[AA];
    __shared__ int   nNbr;
    __shared__ float acc[OUTD];
    __shared__ float shfR_s[NR], shfA_s[NAA], czZ[NZ], szZ[NZ];
    __shared__ float etaR_s, etaA_s, zeta_s;
    // per-pair staging for the split angular phase
    __shared__ float pcos[PCHUNK], psin[PCHUNK];
    __shared__ int   pbase[PCHUNK];
    __shared__ float pf2[PCHUNK][NAA];   // w2 * exp(-etaA*(dsum-ShfA)^2)

    const int tid = threadIdx.x;
    const int bd  = blockDim.x;
    const int i   = blockIdx.x % AA;
    const int b   = blockIdx.x / AA;

    if (tid == 0) {
        nNbr   = 0;
        etaR_s = EtaR[0];
        etaA_s = EtaA[0];
        zeta_s = Zeta[0];
    }
    for (int t = tid; t < AA; t += bd) {
        cxs[t]  = coords[(b*AA + t)*3 + 0];
        cys[t]  = coords[(b*AA + t)*3 + 1];
        czs_[t] = coords[(b*AA + t)*3 + 2];
        sp[t]   = species[b*AA + t];
    }
    for (int t = tid; t < OUTD; t += bd) acc[t] = 0.0f;
    if (tid < NR)  shfR_s[tid] = ShfR[tid];
    if (tid < NAA) shfA_s[tid] = ShfA[tid];
    if (tid < NZ)  { float s = ShfZ[tid]; czZ[tid] = __cosf(s); szZ[tid] = __sinf(s); }
    __syncthreads();

    const bool  validI = (sp[i] >= 0);
    const float xi = cxs[i], yi = cys[i], zi = czs_[i];

    // Per-neighbor distances, cutoffs, compacted angular-neighbor list
    for (int j = tid; j < AA; j += bd) {
        float dx = xi - cxs[j], dy = yi - cys[j], dz = zi - czs_[j];
        float d  = sqrtf(dx*dx + dy*dy + dz*dz);
        dxs[j] = dx; dys[j] = dy; dzs[j] = dz; dst[j] = d;
        bool pv = validI && (sp[j] >= 0) && (j != i);
        fcr[j] = (pv && d <= RCR) ? (0.5f*__cosf(PI_F * d / RCR) + 0.5f) : 0.0f;
        bool an = (pv && d <= RCA);
        fca[j] = an ? (0.5f*__cosf(PI_F * d / RCA) + 0.5f) : 0.0f;
        if (an) { int s = atomicAdd(&nNbr, 1); nbr[s] = j; }
    }
    __syncthreads();

    const int   M      = nNbr;
    const int   npair2 = M*(M-1)/2;
    const float etaR   = etaR_s;
    const float etaA   = etaA_s;
    const float zeta   = zeta_s;

    // ---- Chunked angular, split into phase A (per pair) / phase B (per pair,z) ----
    for (int u0 = 0; u0 < npair2 || u0 == 0; u0 += PCHUNK) {
        const int chunkN = min(PCHUNK, npair2 - u0);

        // Phase A: one thread per pair -> geometry + pre-scaled Gaussians
        if (tid < chunkN) {
            int u = u0 + tid;
            int p = 0, rem = u;
            while (rem >= M - 1 - p) { rem -= M - 1 - p; p++; }
            int q  = p + 1 + rem;
            int jp = nbr[p], jq = nbr[q];

            float dp = dst[jp], dq = dst[jq];
            float dot = dxs[jp]*dxs[jq] + dys[jp]*dys[jq] + dzs[jp]*dzs[jq];
            float dd  = fmaxf(dp*dq, 1e-8f);
            float cosA = 0.95f * dot / dd;
            float sinA = sqrtf(fmaxf(1.0f - cosA*cosA, 0.0f));
            float dsum = 0.5f * (dp + dq);
            float w2   = 2.0f * fca[jp] * fca[jq];

            int s1 = sp[jp], s2 = sp[jq];
            int lo = min(s1, s2), hi = max(s1, s2);
            int pidx = lo*SS - (lo*(lo-1))/2 + (hi - lo);

            pcos[tid]  = cosA;
            psin[tid]  = sinA;
            pbase[tid] = RADD + pidx*(NAA*NZ);
            #pragma unroll
            for (int a = 0; a < NAA; a++) {
                float t = dsum - shfA_s[a];
                pf2[tid][a] = w2 * __expf(-etaA * t * t);
            }
        }

        // Radial phase overlapped with phase A latency (first chunk only);
        // independent smem regions (acc[0..63] vs pair staging / acc[64..]).
        if (u0 == 0) {
            for (int w = tid; w < AA*NR; w += bd) {
                int j = w >> 4;        // NR == 16
                int r = w & 15;
                float f = fcr[j];
                if (f > 0.0f) {
                    float dd = dst[j] - shfR_s[r];
                    float v  = 0.25f * __expf(-etaR * dd * dd) * f;
                    atomicAdd(&acc[sp[j]*NR + r], v);
                }
            }
        }
        __syncthreads();

        // Phase B: one thread per (pair, z) item
        const int nItems = chunkN * NZ;
        for (int w = tid; w < nItems; w += bd) {
            int u = w >> 3;           // NZ == 8
            int z = w & 7;
            float cosA = pcos[u], sinA = psin[u];
            float x = 0.5f * (1.0f + cosA*czZ[z] + sinA*szZ[z]);
            float f1;
            if (zeta == 32.0f) {
                float x2 = x*x, x4 = x2*x2, x8 = x4*x4, x16 = x8*x8;
                f1 = x16*x16;
            } else {
                f1 = __powf(x, zeta);
            }
            int base = pbase[u] + z;
            #pragma unroll
            for (int a = 0; a < NAA; a++) {
                atomicAdd(&acc[base + a*NZ], f1 * pf2[u][a]);
            }
        }
        __syncthreads();
    }

    // ---- Write out: [radial (64) | angular (320)] contiguous per atom ----
    float* o = out + (size_t)blockIdx.x * OUTD;
    for (int t = tid; t < OUTD; t += bd) o[t] = acc[t];
}

extern "C" void kernel_launch(void* const* d_in, const int* in_sizes, int n_in,
                              void* d_out, int out_size)
{
    const int*   species = (const int*)  d_in[0];
    const float* coords  = (const float*)d_in[1];
    const float* EtaR    = (const float*)d_in[2];
    const float* ShfR    = (const float*)d_in[3];
    const float* EtaA    = (const float*)d_in[4];
    const float* Zeta    = (const float*)d_in[5];
    const float* ShfA    = (const float*)d_in[6];
    const float* ShfZ    = (const float*)d_in[7];
    float* out = (float*)d_out;

    int B = in_sizes[0] / AA;   // species is [B, A]
    aev_kernel<<<B * AA, 128>>>(species, coords, EtaR, ShfR, EtaA, Zeta,
                                ShfA, ShfZ, out);
}

// round 3
// speedup vs baseline: 2.7936x; 1.0145x over previous
#include <cuda_runtime.h>
#include <math.h>

// Problem constants (fixed by the bench problem)
#define AA     48          // atoms per batch
#define SS     4           // num species
#define NR     16          // num radial shifts (ShfR)
#define NAA    4           // num angular radial shifts (ShfA)
#define NZ     8           // num angular shifts (ShfZ)
#define NPAIRS (SS*(SS+1)/2)   // 10
#define RADD   (SS*NR)         // 64
#define ANGD   (NPAIRS*NAA*NZ) // 320
#define OUTD   (RADD+ANGD)     // 384
#define RCR    5.2f
#define RCA    3.5f
#define PI_F   3.14159265358979323846f
#define PCHUNK 128             // angular pairs processed per chunk

__global__ __launch_bounds__(128) void aev_kernel(
    const int*   __restrict__ species,   // [B, A]
    const float* __restrict__ coords,    // [B, A, 3]
    const float* __restrict__ EtaR,      // [1]
    const float* __restrict__ ShfR,      // [NR]
    const float* __restrict__ EtaA,      // [1]
    const float* __restrict__ Zeta,      // [1]
    const float* __restrict__ ShfA,      // [NAA]
    const float* __restrict__ ShfZ,      // [NZ]
    float*       __restrict__ out)       // [B, A, OUTD]
{
    __shared__ float cxs[AA], cys[AA], czs_[AA];
    __shared__ int   sp[AA];
    __shared__ int   cnt;

    const int tid  = threadIdx.x;
    const int bd   = blockDim.x;
    const int role = blockIdx.x & 1;        // 0 = radial, 1 = angular
    const int aidx = blockIdx.x >> 1;       // global atom index
    const int i    = aidx % AA;
    const int b    = aidx / AA;

    if (tid == 0) cnt = 0;
    if (tid < AA) {
        cxs[tid]  = coords[(b*AA + tid)*3 + 0];
        cys[tid]  = coords[(b*AA + tid)*3 + 1];
        czs_[tid] = coords[(b*AA + tid)*3 + 2];
        sp[tid]   = species[b*AA + tid];
    }
    __syncthreads();

    const bool  validI = (sp[i] >= 0);
    const float xi = cxs[i], yi = cys[i], zi = czs_[i];
    float* o = out + (size_t)aidx * OUTD;

    if (role == 0) {
        // ================= RADIAL: writes out[0..RADD) =================
        __shared__ float rd[AA], rf[AA];
        __shared__ int   rs[AA];
        __shared__ float accR[RADD];
        __shared__ float shfR_s[NR];
        __shared__ float etaR_sh;

        if (tid == 0) etaR_sh = EtaR[0];
        if (tid < NR) shfR_s[tid] = ShfR[tid];
        if (tid < RADD) accR[tid] = 0.0f;

        if (tid < AA) {
            int j = tid;
            float dx = xi - cxs[j], dy = yi - cys[j], dz = zi - czs_[j];
            float d  = sqrtf(dx*dx + dy*dy + dz*dz);
            bool ok = validI && (sp[j] >= 0) && (j != i) && (d <= RCR);
            if (ok) {
                int s = atomicAdd(&cnt, 1);
                rd[s] = d;
                rf[s] = 0.5f*__cosf(PI_F * d * (1.0f/RCR)) + 0.5f;
                rs[s] = sp[j];
            }
        }
        __syncthreads();

        const int   Mr   = cnt;
        const float etaR = etaR_sh;
        for (int w = tid; w < Mr*NR; w += bd) {
            int j = w >> 4;        // NR == 16
            int r = w & 15;
            float dd = rd[j] - shfR_s[r];
            float v  = 0.25f * __expf(-etaR * dd * dd) * rf[j];
            atomicAdd(&accR[rs[j]*NR + r], v);
        }
        __syncthreads();

        if (tid < RADD) o[tid] = accR[tid];
    } else {
        // ================= ANGULAR: writes out[RADD..OUTD) =================
        __shared__ float dxs[AA], dys[AA], dzs[AA], dst[AA], fca[AA];
        __shared__ int   nbr[AA];
        __shared__ float accA[ANGD];
        __shared__ float shfA_s[NAA], czZ[NZ], szZ[NZ];
        __shared__ float etaA_sh, zeta_sh;
        __shared__ float pcos[PCHUNK], psin[PCHUNK];
        __shared__ int   pbase[PCHUNK];
        __shared__ float pf2[PCHUNK][NAA];

        if (tid == 0) { etaA_sh = EtaA[0]; zeta_sh = Zeta[0]; }
        if (tid < NAA) shfA_s[tid] = ShfA[tid];
        if (tid < NZ)  { float s = ShfZ[tid]; czZ[tid] = __cosf(s); szZ[tid] = __sinf(s); }
        for (int t = tid; t < ANGD; t += bd) accA[t] = 0.0f;

        if (tid < AA) {
            int j = tid;
            float dx = xi - cxs[j], dy = yi - cys[j], dz = zi - czs_[j];
            float d  = sqrtf(dx*dx + dy*dy + dz*dz);
            bool an = validI && (sp[j] >= 0) && (j != i) && (d <= RCA);
            if (an) {
                int s = atomicAdd(&cnt, 1);
                nbr[s] = j;
                dxs[j] = dx; dys[j] = dy; dzs[j] = dz; dst[j] = d;
                fca[j] = 0.5f*__cosf(PI_F * d * (1.0f/RCA)) + 0.5f;
            }
        }
        __syncthreads();

        const int   M      = cnt;
        const int   npair2 = M*(M-1)/2;
        const float etaA   = etaA_sh;
        const float zeta   = zeta_sh;

        for (int u0 = 0; u0 < npair2 || u0 == 0; u0 += PCHUNK) {
            const int chunkN = min(PCHUNK, npair2 - u0);

            // Phase A: one thread per pair -> geometry + pre-scaled Gaussians
            if (tid < chunkN) {
                int u = u0 + tid;
                int p = 0, rem = u;
                while (rem >= M - 1 - p) { rem -= M - 1 - p; p++; }
                int q  = p + 1 + rem;
                int jp = nbr[p], jq = nbr[q];

                float dp = dst[jp], dq = dst[jq];
                float dot = dxs[jp]*dxs[jq] + dys[jp]*dys[jq] + dzs[jp]*dzs[jq];
                float dd  = fmaxf(dp*dq, 1e-8f);
                float cosA = 0.95f * dot * __frcp_rn(dd);
                float sinA = sqrtf(fmaxf(1.0f - cosA*cosA, 0.0f));
                float dsum = 0.5f * (dp + dq);
                float w2   = 2.0f * fca[jp] * fca[jq];

                int s1 = sp[jp], s2 = sp[jq];
                int lo = min(s1, s2), hi = max(s1, s2);
                int pidx = lo*SS - (lo*(lo-1))/2 + (hi - lo);

                pcos[tid]  = cosA;
                psin[tid]  = sinA;
                pbase[tid] = pidx*(NAA*NZ);
                #pragma unroll
                for (int a = 0; a < NAA; a++) {
                    float t = dsum - shfA_s[a];
                    pf2[tid][a] = w2 * __expf(-etaA * t * t);
                }
            }
            __syncthreads();

            // Phase B: one thread per (pair, z) item
            const int nItems = chunkN * NZ;
            for (int w = tid; w < nItems; w += bd) {
                int u = w >> 3;           // NZ == 8
                int z = w & 7;
                float cosA = pcos[u], sinA = psin[u];
                float x = 0.5f * (1.0f + cosA*czZ[z] + sinA*szZ[z]);
                float f1;
                if (zeta == 32.0f) {
                    float x2 = x*x, x4 = x2*x2, x8 = x4*x4, x16 = x8*x8;
                    f1 = x16*x16;
                } else {
                    f1 = __powf(x, zeta);
                }
                int base = pbase[u] + z;
                #pragma unroll
                for (int a = 0; a < NAA; a++) {
                    atomicAdd(&accA[base + a*NZ], f1 * pf2[u][a]);
                }
            }
            __syncthreads();
        }

        for (int t = tid; t < ANGD; t += bd) o[RADD + t] = accA[t];
    }
}

extern "C" void kernel_launch(void* const* d_in, const int* in_sizes, int n_in,
                              void* d_out, int out_size)
{
    const int*   species = (const int*)  d_in[0];
    const float* coords  = (const float*)d_in[1];
    const float* EtaR    = (const float*)d_in[2];
    const float* ShfR    = (const float*)d_in[3];
    const float* EtaA    = (const float*)d_in[4];
    const float* Zeta    = (const float*)d_in[5];
    const float* ShfA    = (const float*)d_in[6];
    const float* ShfZ    = (const float*)d_in[7];
    float* out = (float*)d_out;

    int B = in_sizes[0] / AA;   // species is [B, A]
    aev_kernel<<<B * AA * 2, 128>>>(species, coords, EtaR, ShfR, EtaA, Zeta,
                                    ShfA, ShfZ, out);
}